// round 15
// baseline (speedup 1.0000x reference)
#include <cuda_runtime.h>

#define B_  64
#define T_  8192
#define D_  128
#define H1_ 128
#define H2_ 64
#define K_  9

// Emissions scratch (B*T, K) fp32 = 18.9 MB; per-(batch,tile) done flags.
__device__ float g_em[(size_t)B_ * T_ * K_];
__device__ int   g_done[B_ * 128];

#define TOK 64
#define AS  132
#define RSLOTS 72

__global__ void init_kernel() {
    int i = blockIdx.x * 256 + threadIdx.x;
    if (i < B_ * 128) g_done[i] = 0;
}

__device__ __forceinline__ int nib_get(const unsigned char* bpn, int t, int tag) {
    unsigned v = bpn[t * 5 + (tag >> 1)];
    return (int)((v >> ((tag & 1) * 4)) & 0xF);
}

__device__ __forceinline__ float f4c(const float4& v, int s) {
    return s == 0 ? v.x : s == 1 ? v.y : s == 2 ? v.z : v.w;
}

// ---------------------------------------------------------------------------
// Fused kernel. blockIdx 0..63: viterbi consumer (batch b = blockIdx).
//                blockIdx 64..8255: MLP producer tile (tau-major over batches).
// MLP path: R9 layout, but activation loads vectorized along k (LDS.128 quads).
// Viterbi path: byte-identical to the R14 winner (3-way split producer).
// ---------------------------------------------------------------------------
__global__ void __launch_bounds__(256) fused_kernel(
    const float* __restrict__ x,  const float* __restrict__ W1, const float* __restrict__ b1,
    const float* __restrict__ W2, const float* __restrict__ b2,
    const float* __restrict__ W3, const float* __restrict__ b3,
    const float* __restrict__ st, const float* __restrict__ et,
    const float* __restrict__ trans, float* __restrict__ out)
{
    __shared__ union {
        struct {
            float sA[TOK * AS]; float sW[2048]; float sW3[576];
            float sB1[128]; float sB2[64]; float sB3[16];
        } m;
        struct {
            unsigned char sBpN[T_ * 5];   // 40960 B backpointers
            float sRing[RSLOTS * 12 + 32];
            float sEm[3][320];
            int   sB[128];
        } v;
    } smu;

    const int tid = threadIdx.x;

    // ======================= MLP producer path =======================
    if (blockIdx.x >= 64) {
        const int bm  = blockIdx.x - 64;
        const int tau = bm >> 6;
        const int b   = bm & 63;
        const size_t nb = (size_t)b * T_ + (size_t)tau * TOK;

        float* sA  = smu.m.sA;  float* sW  = smu.m.sW;  float* sW3 = smu.m.sW3;
        float* sB1 = smu.m.sB1; float* sB2 = smu.m.sB2; float* sB3 = smu.m.sB3;

        {
            const float4* xv = (const float4*)(x + nb * D_);
            #pragma unroll
            for (int it = 0; it < 8; ++it) {
                int vq  = tid + it * 256;
                int tok = vq >> 5;
                int d4  = vq & 31;
                *(float4*)&sA[tok * AS + d4 * 4] = xv[vq];
            }
        }
        if (tid < 128) sB1[tid] = b1[tid];
        if (tid < 64)  sB2[tid] = b2[tid];
        if (tid < 9)   sB3[tid] = b3[tid];
        for (int k = tid; k < 576; k += 256) sW3[k] = W3[k];

        // stage 1: h1 = relu(x @ W1 + b1), 8 tok x 4 out per thread.
        // Activation loads vectorized: one LDS.128 per token per 4 k-steps.
        {
            const int tx = tid & 31, ty = tid >> 5;
            const int o0 = tx * 4, t0 = ty * 8;
            float acc[8][4];
            #pragma unroll
            for (int i = 0; i < 8; ++i)
                #pragma unroll
                for (int j = 0; j < 4; ++j) acc[i][j] = 0.f;

            const float4* w1v = (const float4*)W1;
            float4* sWv = (float4*)sW;
            for (int p = 0; p < 8; ++p) {
                __syncthreads();
                sWv[tid]       = w1v[p * 512 + tid];
                sWv[tid + 256] = w1v[p * 512 + tid + 256];
                __syncthreads();
                #pragma unroll
                for (int kq = 0; kq < 4; ++kq) {       // 4 quads of k
                    const int k0 = p * 16 + kq * 4;
                    float4 av[8];
                    #pragma unroll
                    for (int i = 0; i < 8; ++i)
                        av[i] = *(const float4*)&sA[(t0 + i) * AS + k0];
                    #pragma unroll
                    for (int s = 0; s < 4; ++s) {      // ascending k order
                        float4 w = *(const float4*)&sW[(kq * 4 + s) * 128 + o0];
                        #pragma unroll
                        for (int i = 0; i < 8; ++i) {
                            float a = f4c(av[i], s);
                            acc[i][0] = fmaf(a, w.x, acc[i][0]);
                            acc[i][1] = fmaf(a, w.y, acc[i][1]);
                            acc[i][2] = fmaf(a, w.z, acc[i][2]);
                            acc[i][3] = fmaf(a, w.w, acc[i][3]);
                        }
                    }
                }
            }
            __syncthreads();
            float4 bb = *(const float4*)&sB1[o0];
            #pragma unroll
            for (int i = 0; i < 8; ++i) {
                float4 vv;
                vv.x = acc[i][0] + bb.x; vv.x = vv.x > 0.f ? vv.x : 0.f;
                vv.y = acc[i][1] + bb.y; vv.y = vv.y > 0.f ? vv.y : 0.f;
                vv.z = acc[i][2] + bb.z; vv.z = vv.z > 0.f ? vv.z : 0.f;
                vv.w = acc[i][3] + bb.w; vv.w = vv.w > 0.f ? vv.w : 0.f;
                *(float4*)&sA[(t0 + i) * AS + o0] = vv;
            }
        }

        // stage 2: h2 = relu(h1 @ W2 + b2), 4 tok x 4 out per thread.
        {
            const int tx = tid & 15, ty = tid >> 4;
            const int o0 = tx * 4, t0 = ty * 4;
            float acc[4][4];
            #pragma unroll
            for (int i = 0; i < 4; ++i)
                #pragma unroll
                for (int j = 0; j < 4; ++j) acc[i][j] = 0.f;

            const float4* w2v = (const float4*)W2;
            float4* sWv = (float4*)sW;
            for (int p = 0; p < 8; ++p) {
                __syncthreads();
                sWv[tid] = w2v[p * 256 + tid];
                __syncthreads();
                #pragma unroll
                for (int kq = 0; kq < 4; ++kq) {
                    const int k0 = p * 16 + kq * 4;
                    float4 av[4];
                    #pragma unroll
                    for (int i = 0; i < 4; ++i)
                        av[i] = *(const float4*)&sA[(t0 + i) * AS + k0];
                    #pragma unroll
                    for (int s = 0; s < 4; ++s) {
                        float4 w = *(const float4*)&sW[(kq * 4 + s) * 64 + o0];
                        #pragma unroll
                        for (int i = 0; i < 4; ++i) {
                            float a = f4c(av[i], s);
                            acc[i][0] = fmaf(a, w.x, acc[i][0]);
                            acc[i][1] = fmaf(a, w.y, acc[i][1]);
                            acc[i][2] = fmaf(a, w.z, acc[i][2]);
                            acc[i][3] = fmaf(a, w.w, acc[i][3]);
                        }
                    }
                }
            }
            __syncthreads();
            float4 bb = *(const float4*)&sB2[o0];
            #pragma unroll
            for (int i = 0; i < 4; ++i) {
                float4 vv;
                vv.x = acc[i][0] + bb.x; vv.x = vv.x > 0.f ? vv.x : 0.f;
                vv.y = acc[i][1] + bb.y; vv.y = vv.y > 0.f ? vv.y : 0.f;
                vv.z = acc[i][2] + bb.z; vv.z = vv.z > 0.f ? vv.z : 0.f;
                vv.w = acc[i][3] + bb.w; vv.w = vv.w > 0.f ? vv.w : 0.f;
                *(float4*)&sA[(t0 + i) * AS + o0] = vv;
            }
        }
        __syncthreads();

        // stage 3: em = h2 @ W3 + b3, then release this tile
        if (tid < TOK) {
            const int tok = tid;
            float e[9];
            #pragma unroll
            for (int j = 0; j < 9; ++j) e[j] = 0.f;
            for (int k = 0; k < 64; ++k) {
                float h = sA[tok * AS + k];
                #pragma unroll
                for (int j = 0; j < 9; ++j)
                    e[j] = fmaf(h, sW3[k * 9 + j], e[j]);
            }
            float* dst = g_em + (nb + tok) * K_;
            #pragma unroll
            for (int j = 0; j < 9; ++j) dst[j] = e[j] + sB3[j];
            __threadfence();   // per-writer release fence
        }
        __syncthreads();
        if (tid == 0) {
            __threadfence();
            atomicExch(&g_done[b * 128 + tau], 1);
        }
        return;
    }

    // ======================= Viterbi consumer path (R14 verbatim) ==========
    unsigned char* sBpN = smu.v.sBpN;
    float* sRing = smu.v.sRing;
    int*   sB    = smu.v.sB;

    const int wid  = tid >> 5;
    const int lane = tid & 31;
    const int b    = blockIdx.x;
    const float* emb = g_em + (size_t)b * T_ * K_;
    const bool act = lane < K_;
    volatile int* done = (volatile int*)&g_done[b * 128];

    float tc0=0,tc1=0,tc2=0,tc3=0,tc4=0,tc5=0,tc6=0,tc7=0,tc8=0;
    int g3 = 0; float tcA=0, tcB=0, tcC=0;
    if (wid == 0) {
        int l  = (lane < 27) ? lane : lane - 27;
        int g  = l / 9;
        int jj = l - g * 9;
        g3 = 3 * g;
        tcA = trans[(g3 + 0) * 9 + jj];
        tcB = trans[(g3 + 1) * 9 + jj];
        tcC = trans[(g3 + 2) * 9 + jj];
    } else if (act) {
        tc0 = trans[0*K_+lane]; tc1 = trans[1*K_+lane]; tc2 = trans[2*K_+lane];
        tc3 = trans[3*K_+lane]; tc4 = trans[4*K_+lane]; tc5 = trans[5*K_+lane];
        tc6 = trans[6*K_+lane]; tc7 = trans[7*K_+lane]; tc8 = trans[8*K_+lane];
    }

    if (tid == 0) {
        while (done[0] == 0) { }
        __threadfence();
    }
    __syncthreads();

    for (int i = tid; i < 288; i += 256) smu.v.sEm[0][i] = emb[9 + i];
    float sv = 0.f;
    if (wid == 0 && act) {
        sv = st[lane] + emb[lane];              // reference add order
        sRing[0 * 12 + lane] = sv;
    }
    __syncthreads();

    int ws  = 1;
    int sp0 = 0;
    int frontier = 1;

    for (int c = 0; c <= 256; ++c) {
        if (wid == 0) {
            if (c <= 255) {
                int tmax = 32 * c + 64; if (tmax > 8191) tmax = 8191;
                int need = (tmax >> 6) + 1;
                if (frontier < need) {
                    do {
                        while (done[frontier] == 0) { }
                        ++frontier;
                    } while (frontier < need);
                    __threadfence();   // acquire
                }

                float pref[9];
                const int cn = c + 1;
                int nnext = 0;
                if (cn <= 255) nnext = min(32, 8191 - 32 * cn);
                const int t0n = 1 + 32 * cn;
                #pragma unroll
                for (int k = 0; k < 9; ++k) {
                    int idx = lane + k * 32;
                    pref[k] = (idx < nnext * 9) ? emb[(size_t)t0n * 9 + idx] : 0.f;
                }

                const int ns = min(32, 8191 - 32 * c);
                const float* buf = smu.v.sEm[c % 3];
                #pragma unroll 2
                for (int q = 0; q < ns; ++q) {
                    float e  = buf[q * 9 + lane];
                    float s0 = __shfl_sync(0xffffffffu, sv, g3);
                    float s1 = __shfl_sync(0xffffffffu, sv, g3 + 1);
                    float s2 = __shfl_sync(0xffffffffu, sv, g3 + 2);
                    float p  = fmaxf(fmaxf(s0 + tcA, s1 + tcB), s2 + tcC);
                    float r1 = __shfl_sync(0xffffffffu, p, lane + 9);
                    float r2 = __shfl_sync(0xffffffffu, p, (lane + 18) & 31);
                    float m  = fmaxf(fmaxf(p, r1), r2);
                    sv = m + e;                    // == max(cd_with_e) bitwise
                    if (act) sRing[ws * 12 + lane] = sv;
                    ws = (ws + 1 == RSLOTS) ? 0 : ws + 1;
                }
                if (cn <= 255) {
                    float* nb2 = smu.v.sEm[cn % 3];
                    #pragma unroll
                    for (int k = 0; k < 9; ++k) nb2[lane + k * 32] = pref[k];
                }
            }
        }
        else if (wid <= 3 && c >= 1) {
            const int cc = c - 1;
            const int t0 = 1 + 32 * cc;
            const int ns = min(32, 8191 - 32 * cc);
            int qlo = 11 * (wid - 1);
            int qhi = (wid == 3) ? ns : min(11 * wid, ns);
            if (qlo > ns) qlo = ns;
            const float* buf = smu.v.sEm[cc % 3];
            int sp = sp0 + qlo; if (sp >= RSLOTS) sp -= RSLOTS;
            for (int q = qlo; q < qhi; ++q) {
                float4 p0 = *(const float4*)&sRing[sp * 12];
                float4 p1 = *(const float4*)&sRing[sp * 12 + 4];
                float  s8 = sRing[sp * 12 + 8];
                int sc = (sp + 1 == RSLOTS) ? 0 : sp + 1;
                float m = sRing[sc * 12 + lane];     // s_t[lane]
                float e = buf[q * 9 + lane];
                float cd0 = (p0.x + tc0) + e;        // exact reference order
                float cd1 = (p0.y + tc1) + e;
                float cd2 = (p0.z + tc2) + e;
                float cd3 = (p0.w + tc3) + e;
                float cd4 = (p1.x + tc4) + e;
                float cd5 = (p1.y + tc5) + e;
                float cd6 = (p1.z + tc6) + e;
                float cd7 = (p1.w + tc7) + e;
                float cd8 = (s8   + tc8) + e;
                unsigned mk = (cd0 == m ? 1u   : 0u) | (cd1 == m ? 2u   : 0u)
                            | (cd2 == m ? 4u   : 0u) | (cd3 == m ? 8u   : 0u)
                            | (cd4 == m ? 16u  : 0u) | (cd5 == m ? 32u  : 0u)
                            | (cd6 == m ? 64u  : 0u) | (cd7 == m ? 128u : 0u)
                            | (cd8 == m ? 256u : 0u);
                int bp = __ffs(mk) - 1;              // first-max (jnp.argmax)
                int bpn = __shfl_down_sync(0xffffffffu, bp, 1);
                if (act && ((lane & 1) == 0)) {
                    unsigned char byte = (lane == 8)
                        ? (unsigned char)bp
                        : (unsigned char)(bp | (bpn << 4));
                    sBpN[(t0 + q) * 5 + (lane >> 1)] = byte;
                }
                sp = sc;
            }
        }
        if (c >= 1) { sp0 += 32; if (sp0 >= RSLOTS) sp0 -= RSLOTS; }
        __syncthreads();
    }

    // ---------------- backtrack: 3-phase parallel, exact chase -------------
    unsigned char* sMap = (unsigned char*)sRing;   // 1152 B alias (slots 0..23)
    // final s vector: slot 8191 % 72 = 55 (byte 2640) — outside alias.

    if (tid < 128) {
        #pragma unroll 1
        for (int k = 0; k < 3; ++k) {
            int u1 = tid + 128 * k;
            int u2 = tid + 128 * (k + 3);
            int u3 = tid + 128 * (k + 6);
            int q1 = u1 / 9, j1 = u1 - q1 * 9;
            int q2 = u2 / 9, j2 = u2 - q2 * 9;
            int q3 = u3 / 9, j3 = u3 - q3 * 9;
            int t1 = min(64 * q1 + 64, 8191), lo1 = 64 * q1;
            int t2 = min(64 * q2 + 64, 8191), lo2 = 64 * q2;
            int t3 = min(64 * q3 + 64, 8191), lo3 = 64 * q3;
            int g1 = j1, g2 = j2, g3b = j3;
            #pragma unroll 1
            for (int s = 0; s < 64; ++s) {
                if (t1 > lo1) { g1 = nib_get(sBpN, t1, g1); --t1; }
                if (t2 > lo2) { g2 = nib_get(sBpN, t2, g2); --t2; }
                if (t3 > lo3) { g3b = nib_get(sBpN, t3, g3b); --t3; }
            }
            sMap[u1] = (unsigned char)g1;
            sMap[u2] = (unsigned char)g2;
            sMap[u3] = (unsigned char)g3b;
        }
    }
    __syncthreads();

    if (tid == 0) {
        const float* sf = &sRing[55 * 12];          // s_{8191}
        float best = sf[0] + et[0];
        int last = 0;
        #pragma unroll
        for (int j = 1; j < 9; ++j) {
            float v = sf[j] + et[j];
            if (v > best) { best = v; last = j; }   // strict >: first max
        }
        int tag = last;
        sB[127] = tag;
        for (int q = 127; q >= 1; --q) {
            tag = sMap[q * 9 + tag];
            sB[q - 1] = tag;
        }
    }
    __syncthreads();

    if (tid < 128) {
        float* ob = out + (size_t)b * T_;
        int q = tid;
        int thi = min(64 * q + 64, 8191);
        int tlo = 64 * q;
        int tag = sB[q];
        if (q == 127) ob[8191] = (float)tag;
        for (int t = thi; t > tlo; --t) {
            tag = nib_get(sBpN, t, tag);
            ob[t - 1] = (float)tag;
        }
    }
}

// ---------------------------------------------------------------------------
extern "C" void kernel_launch(void* const* d_in, const int* in_sizes, int n_in,
                              void* d_out, int out_size)
{
    int ix = 0, iW1 = 1, ib1 = 2, iW2 = 3, ib2 = 4, iW3 = 5, itr = 9;
    int nine[3] = {6, 7, 8};
    int n9 = 0;
    for (int i = 0; i < n_in; ++i) {
        long long s = in_sizes[i];
        if (s == 67108864LL)      ix  = i;
        else if (s == 16384)      iW1 = i;
        else if (s == 128)        ib1 = i;
        else if (s == 8192)       iW2 = i;
        else if (s == 64)         ib2 = i;
        else if (s == 576)        iW3 = i;
        else if (s == 81)         itr = i;
        else if (s == 9) { if (n9 < 3) nine[n9++] = i; }
    }
    const float* x  = (const float*)d_in[ix];
    const float* W1 = (const float*)d_in[iW1];
    const float* b1 = (const float*)d_in[ib1];
    const float* W2 = (const float*)d_in[iW2];
    const float* b2 = (const float*)d_in[ib2];
    const float* W3 = (const float*)d_in[iW3];
    const float* b3 = (const float*)d_in[nine[0]];
    const float* st = (const float*)d_in[nine[1]];
    const float* et = (const float*)d_in[nine[2]];
    const float* tr = (const float*)d_in[itr];
    float* out = (float*)d_out;

    init_kernel<<<32, 256>>>();
    fused_kernel<<<64 + (B_ * T_) / TOK, 256>>>(x, W1, b1, W2, b2, W3, b3,
                                                st, et, tr, out);
}

// round 16
// speedup vs baseline: 1.0878x; 1.0878x over previous
#include <cuda_runtime.h>

#define B_  64
#define T_  8192
#define D_  128
#define H1_ 128
#define H2_ 64
#define K_  9

// Emissions scratch (B*T, K) fp32 = 18.9 MB; per-(batch,tile) done flags.
__device__ float g_em[(size_t)B_ * T_ * K_];
__device__ int   g_done[B_ * 128];

#define TOK 64
#define AS  132
#define RSLOTS 72
#define OCC_PAD 30720   // unused dynamic smem: forces 2 blocks/SM (placement fence)

__global__ void init_kernel() {
    int i = blockIdx.x * 256 + threadIdx.x;
    if (i < B_ * 128) g_done[i] = 0;
}

__device__ __forceinline__ int nib_get(const unsigned char* bpn, int t, int tag) {
    unsigned v = bpn[t * 5 + (tag >> 1)];
    return (int)((v >> ((tag & 1) * 4)) & 0xF);
}

__device__ __forceinline__ float f4c(const float4& v, int s) {
    return s == 0 ? v.x : s == 1 ? v.y : s == 2 ? v.z : v.w;
}

// ---------------------------------------------------------------------------
// Fused kernel. blockIdx 0..63: viterbi consumer (batch b = blockIdx).
//                blockIdx 64..8255: MLP producer tile (tau-major over batches).
// Device code byte-identical to R15; only the launch adds an occupancy pad.
// ---------------------------------------------------------------------------
__global__ void __launch_bounds__(256) fused_kernel(
    const float* __restrict__ x,  const float* __restrict__ W1, const float* __restrict__ b1,
    const float* __restrict__ W2, const float* __restrict__ b2,
    const float* __restrict__ W3, const float* __restrict__ b3,
    const float* __restrict__ st, const float* __restrict__ et,
    const float* __restrict__ trans, float* __restrict__ out)
{
    __shared__ union {
        struct {
            float sA[TOK * AS]; float sW[2048]; float sW3[576];
            float sB1[128]; float sB2[64]; float sB3[16];
        } m;
        struct {
            unsigned char sBpN[T_ * 5];   // 40960 B backpointers
            float sRing[RSLOTS * 12 + 32];
            float sEm[3][320];
            int   sB[128];
        } v;
    } smu;

    const int tid = threadIdx.x;

    // ======================= MLP producer path =======================
    if (blockIdx.x >= 64) {
        const int bm  = blockIdx.x - 64;
        const int tau = bm >> 6;
        const int b   = bm & 63;
        const size_t nb = (size_t)b * T_ + (size_t)tau * TOK;

        float* sA  = smu.m.sA;  float* sW  = smu.m.sW;  float* sW3 = smu.m.sW3;
        float* sB1 = smu.m.sB1; float* sB2 = smu.m.sB2; float* sB3 = smu.m.sB3;

        {
            const float4* xv = (const float4*)(x + nb * D_);
            #pragma unroll
            for (int it = 0; it < 8; ++it) {
                int vq  = tid + it * 256;
                int tok = vq >> 5;
                int d4  = vq & 31;
                *(float4*)&sA[tok * AS + d4 * 4] = xv[vq];
            }
        }
        if (tid < 128) sB1[tid] = b1[tid];
        if (tid < 64)  sB2[tid] = b2[tid];
        if (tid < 9)   sB3[tid] = b3[tid];
        for (int k = tid; k < 576; k += 256) sW3[k] = W3[k];

        // stage 1: h1 = relu(x @ W1 + b1), 8 tok x 4 out per thread.
        {
            const int tx = tid & 31, ty = tid >> 5;
            const int o0 = tx * 4, t0 = ty * 8;
            float acc[8][4];
            #pragma unroll
            for (int i = 0; i < 8; ++i)
                #pragma unroll
                for (int j = 0; j < 4; ++j) acc[i][j] = 0.f;

            const float4* w1v = (const float4*)W1;
            float4* sWv = (float4*)sW;
            for (int p = 0; p < 8; ++p) {
                __syncthreads();
                sWv[tid]       = w1v[p * 512 + tid];
                sWv[tid + 256] = w1v[p * 512 + tid + 256];
                __syncthreads();
                #pragma unroll
                for (int kq = 0; kq < 4; ++kq) {
                    const int k0 = p * 16 + kq * 4;
                    float4 av[8];
                    #pragma unroll
                    for (int i = 0; i < 8; ++i)
                        av[i] = *(const float4*)&sA[(t0 + i) * AS + k0];
                    #pragma unroll
                    for (int s = 0; s < 4; ++s) {      // ascending k order
                        float4 w = *(const float4*)&sW[(kq * 4 + s) * 128 + o0];
                        #pragma unroll
                        for (int i = 0; i < 8; ++i) {
                            float a = f4c(av[i], s);
                            acc[i][0] = fmaf(a, w.x, acc[i][0]);
                            acc[i][1] = fmaf(a, w.y, acc[i][1]);
                            acc[i][2] = fmaf(a, w.z, acc[i][2]);
                            acc[i][3] = fmaf(a, w.w, acc[i][3]);
                        }
                    }
                }
            }
            __syncthreads();
            float4 bb = *(const float4*)&sB1[o0];
            #pragma unroll
            for (int i = 0; i < 8; ++i) {
                float4 vv;
                vv.x = acc[i][0] + bb.x; vv.x = vv.x > 0.f ? vv.x : 0.f;
                vv.y = acc[i][1] + bb.y; vv.y = vv.y > 0.f ? vv.y : 0.f;
                vv.z = acc[i][2] + bb.z; vv.z = vv.z > 0.f ? vv.z : 0.f;
                vv.w = acc[i][3] + bb.w; vv.w = vv.w > 0.f ? vv.w : 0.f;
                *(float4*)&sA[(t0 + i) * AS + o0] = vv;
            }
        }

        // stage 2: h2 = relu(h1 @ W2 + b2), 4 tok x 4 out per thread.
        {
            const int tx = tid & 15, ty = tid >> 4;
            const int o0 = tx * 4, t0 = ty * 4;
            float acc[4][4];
            #pragma unroll
            for (int i = 0; i < 4; ++i)
                #pragma unroll
                for (int j = 0; j < 4; ++j) acc[i][j] = 0.f;

            const float4* w2v = (const float4*)W2;
            float4* sWv = (float4*)sW;
            for (int p = 0; p < 8; ++p) {
                __syncthreads();
                sWv[tid] = w2v[p * 256 + tid];
                __syncthreads();
                #pragma unroll
                for (int kq = 0; kq < 4; ++kq) {
                    const int k0 = p * 16 + kq * 4;
                    float4 av[4];
                    #pragma unroll
                    for (int i = 0; i < 4; ++i)
                        av[i] = *(const float4*)&sA[(t0 + i) * AS + k0];
                    #pragma unroll
                    for (int s = 0; s < 4; ++s) {
                        float4 w = *(const float4*)&sW[(kq * 4 + s) * 64 + o0];
                        #pragma unroll
                        for (int i = 0; i < 4; ++i) {
                            float a = f4c(av[i], s);
                            acc[i][0] = fmaf(a, w.x, acc[i][0]);
                            acc[i][1] = fmaf(a, w.y, acc[i][1]);
                            acc[i][2] = fmaf(a, w.z, acc[i][2]);
                            acc[i][3] = fmaf(a, w.w, acc[i][3]);
                        }
                    }
                }
            }
            __syncthreads();
            float4 bb = *(const float4*)&sB2[o0];
            #pragma unroll
            for (int i = 0; i < 4; ++i) {
                float4 vv;
                vv.x = acc[i][0] + bb.x; vv.x = vv.x > 0.f ? vv.x : 0.f;
                vv.y = acc[i][1] + bb.y; vv.y = vv.y > 0.f ? vv.y : 0.f;
                vv.z = acc[i][2] + bb.z; vv.z = vv.z > 0.f ? vv.z : 0.f;
                vv.w = acc[i][3] + bb.w; vv.w = vv.w > 0.f ? vv.w : 0.f;
                *(float4*)&sA[(t0 + i) * AS + o0] = vv;
            }
        }
        __syncthreads();

        // stage 3: em = h2 @ W3 + b3, then release this tile
        if (tid < TOK) {
            const int tok = tid;
            float e[9];
            #pragma unroll
            for (int j = 0; j < 9; ++j) e[j] = 0.f;
            for (int k = 0; k < 64; ++k) {
                float h = sA[tok * AS + k];
                #pragma unroll
                for (int j = 0; j < 9; ++j)
                    e[j] = fmaf(h, sW3[k * 9 + j], e[j]);
            }
            float* dst = g_em + (nb + tok) * K_;
            #pragma unroll
            for (int j = 0; j < 9; ++j) dst[j] = e[j] + sB3[j];
            __threadfence();   // per-writer release fence
        }
        __syncthreads();
        if (tid == 0) {
            __threadfence();
            atomicExch(&g_done[b * 128 + tau], 1);
        }
        return;
    }

    // ======================= Viterbi consumer path (R14 verbatim) ==========
    unsigned char* sBpN = smu.v.sBpN;
    float* sRing = smu.v.sRing;
    int*   sB    = smu.v.sB;

    const int wid  = tid >> 5;
    const int lane = tid & 31;
    const int b    = blockIdx.x;
    const float* emb = g_em + (size_t)b * T_ * K_;
    const bool act = lane < K_;
    volatile int* done = (volatile int*)&g_done[b * 128];

    float tc0=0,tc1=0,tc2=0,tc3=0,tc4=0,tc5=0,tc6=0,tc7=0,tc8=0;
    int g3 = 0; float tcA=0, tcB=0, tcC=0;
    if (wid == 0) {
        int l  = (lane < 27) ? lane : lane - 27;
        int g  = l / 9;
        int jj = l - g * 9;
        g3 = 3 * g;
        tcA = trans[(g3 + 0) * 9 + jj];
        tcB = trans[(g3 + 1) * 9 + jj];
        tcC = trans[(g3 + 2) * 9 + jj];
    } else if (act) {
        tc0 = trans[0*K_+lane]; tc1 = trans[1*K_+lane]; tc2 = trans[2*K_+lane];
        tc3 = trans[3*K_+lane]; tc4 = trans[4*K_+lane]; tc5 = trans[5*K_+lane];
        tc6 = trans[6*K_+lane]; tc7 = trans[7*K_+lane]; tc8 = trans[8*K_+lane];
    }

    if (tid == 0) {
        while (done[0] == 0) { }
        __threadfence();
    }
    __syncthreads();

    for (int i = tid; i < 288; i += 256) smu.v.sEm[0][i] = emb[9 + i];
    float sv = 0.f;
    if (wid == 0 && act) {
        sv = st[lane] + emb[lane];              // reference add order
        sRing[0 * 12 + lane] = sv;
    }
    __syncthreads();

    int ws  = 1;
    int sp0 = 0;
    int frontier = 1;

    for (int c = 0; c <= 256; ++c) {
        if (wid == 0) {
            if (c <= 255) {
                int tmax = 32 * c + 64; if (tmax > 8191) tmax = 8191;
                int need = (tmax >> 6) + 1;
                if (frontier < need) {
                    do {
                        while (done[frontier] == 0) { }
                        ++frontier;
                    } while (frontier < need);
                    __threadfence();   // acquire
                }

                float pref[9];
                const int cn = c + 1;
                int nnext = 0;
                if (cn <= 255) nnext = min(32, 8191 - 32 * cn);
                const int t0n = 1 + 32 * cn;
                #pragma unroll
                for (int k = 0; k < 9; ++k) {
                    int idx = lane + k * 32;
                    pref[k] = (idx < nnext * 9) ? emb[(size_t)t0n * 9 + idx] : 0.f;
                }

                const int ns = min(32, 8191 - 32 * c);
                const float* buf = smu.v.sEm[c % 3];
                #pragma unroll 2
                for (int q = 0; q < ns; ++q) {
                    float e  = buf[q * 9 + lane];
                    float s0 = __shfl_sync(0xffffffffu, sv, g3);
                    float s1 = __shfl_sync(0xffffffffu, sv, g3 + 1);
                    float s2 = __shfl_sync(0xffffffffu, sv, g3 + 2);
                    float p  = fmaxf(fmaxf(s0 + tcA, s1 + tcB), s2 + tcC);
                    float r1 = __shfl_sync(0xffffffffu, p, lane + 9);
                    float r2 = __shfl_sync(0xffffffffu, p, (lane + 18) & 31);
                    float m  = fmaxf(fmaxf(p, r1), r2);
                    sv = m + e;                    // == max(cd_with_e) bitwise
                    if (act) sRing[ws * 12 + lane] = sv;
                    ws = (ws + 1 == RSLOTS) ? 0 : ws + 1;
                }
                if (cn <= 255) {
                    float* nb2 = smu.v.sEm[cn % 3];
                    #pragma unroll
                    for (int k = 0; k < 9; ++k) nb2[lane + k * 32] = pref[k];
                }
            }
        }
        else if (wid <= 3 && c >= 1) {
            const int cc = c - 1;
            const int t0 = 1 + 32 * cc;
            const int ns = min(32, 8191 - 32 * cc);
            int qlo = 11 * (wid - 1);
            int qhi = (wid == 3) ? ns : min(11 * wid, ns);
            if (qlo > ns) qlo = ns;
            const float* buf = smu.v.sEm[cc % 3];
            int sp = sp0 + qlo; if (sp >= RSLOTS) sp -= RSLOTS;
            for (int q = qlo; q < qhi; ++q) {
                float4 p0 = *(const float4*)&sRing[sp * 12];
                float4 p1 = *(const float4*)&sRing[sp * 12 + 4];
                float  s8 = sRing[sp * 12 + 8];
                int sc = (sp + 1 == RSLOTS) ? 0 : sp + 1;
                float m = sRing[sc * 12 + lane];     // s_t[lane]
                float e = buf[q * 9 + lane];
                float cd0 = (p0.x + tc0) + e;        // exact reference order
                float cd1 = (p0.y + tc1) + e;
                float cd2 = (p0.z + tc2) + e;
                float cd3 = (p0.w + tc3) + e;
                float cd4 = (p1.x + tc4) + e;
                float cd5 = (p1.y + tc5) + e;
                float cd6 = (p1.z + tc6) + e;
                float cd7 = (p1.w + tc7) + e;
                float cd8 = (s8   + tc8) + e;
                unsigned mk = (cd0 == m ? 1u   : 0u) | (cd1 == m ? 2u   : 0u)
                            | (cd2 == m ? 4u   : 0u) | (cd3 == m ? 8u   : 0u)
                            | (cd4 == m ? 16u  : 0u) | (cd5 == m ? 32u  : 0u)
                            | (cd6 == m ? 64u  : 0u) | (cd7 == m ? 128u : 0u)
                            | (cd8 == m ? 256u : 0u);
                int bp = __ffs(mk) - 1;              // first-max (jnp.argmax)
                int bpn = __shfl_down_sync(0xffffffffu, bp, 1);
                if (act && ((lane & 1) == 0)) {
                    unsigned char byte = (lane == 8)
                        ? (unsigned char)bp
                        : (unsigned char)(bp | (bpn << 4));
                    sBpN[(t0 + q) * 5 + (lane >> 1)] = byte;
                }
                sp = sc;
            }
        }
        if (c >= 1) { sp0 += 32; if (sp0 >= RSLOTS) sp0 -= RSLOTS; }
        __syncthreads();
    }

    // ---------------- backtrack: 3-phase parallel, exact chase -------------
    unsigned char* sMap = (unsigned char*)sRing;   // 1152 B alias (slots 0..23)
    // final s vector: slot 8191 % 72 = 55 (byte 2640) — outside alias.

    if (tid < 128) {
        #pragma unroll 1
        for (int k = 0; k < 3; ++k) {
            int u1 = tid + 128 * k;
            int u2 = tid + 128 * (k + 3);
            int u3 = tid + 128 * (k + 6);
            int q1 = u1 / 9, j1 = u1 - q1 * 9;
            int q2 = u2 / 9, j2 = u2 - q2 * 9;
            int q3 = u3 / 9, j3 = u3 - q3 * 9;
            int t1 = min(64 * q1 + 64, 8191), lo1 = 64 * q1;
            int t2 = min(64 * q2 + 64, 8191), lo2 = 64 * q2;
            int t3 = min(64 * q3 + 64, 8191), lo3 = 64 * q3;
            int g1 = j1, g2 = j2, g3b = j3;
            #pragma unroll 1
            for (int s = 0; s < 64; ++s) {
                if (t1 > lo1) { g1 = nib_get(sBpN, t1, g1); --t1; }
                if (t2 > lo2) { g2 = nib_get(sBpN, t2, g2); --t2; }
                if (t3 > lo3) { g3b = nib_get(sBpN, t3, g3b); --t3; }
            }
            sMap[u1] = (unsigned char)g1;
            sMap[u2] = (unsigned char)g2;
            sMap[u3] = (unsigned char)g3b;
        }
    }
    __syncthreads();

    if (tid == 0) {
        const float* sf = &sRing[55 * 12];          // s_{8191}
        float best = sf[0] + et[0];
        int last = 0;
        #pragma unroll
        for (int j = 1; j < 9; ++j) {
            float v = sf[j] + et[j];
            if (v > best) { best = v; last = j; }   // strict >: first max
        }
        int tag = last;
        sB[127] = tag;
        for (int q = 127; q >= 1; --q) {
            tag = sMap[q * 9 + tag];
            sB[q - 1] = tag;
        }
    }
    __syncthreads();

    if (tid < 128) {
        float* ob = out + (size_t)b * T_;
        int q = tid;
        int thi = min(64 * q + 64, 8191);
        int tlo = 64 * q;
        int tag = sB[q];
        if (q == 127) ob[8191] = (float)tag;
        for (int t = thi; t > tlo; --t) {
            tag = nib_get(sBpN, t, tag);
            ob[t - 1] = (float)tag;
        }
    }
}

// ---------------------------------------------------------------------------
extern "C" void kernel_launch(void* const* d_in, const int* in_sizes, int n_in,
                              void* d_out, int out_size)
{
    int ix = 0, iW1 = 1, ib1 = 2, iW2 = 3, ib2 = 4, iW3 = 5, itr = 9;
    int nine[3] = {6, 7, 8};
    int n9 = 0;
    for (int i = 0; i < n_in; ++i) {
        long long s = in_sizes[i];
        if (s == 67108864LL)      ix  = i;
        else if (s == 16384)      iW1 = i;
        else if (s == 128)        ib1 = i;
        else if (s == 8192)       iW2 = i;
        else if (s == 64)         ib2 = i;
        else if (s == 576)        iW3 = i;
        else if (s == 81)         itr = i;
        else if (s == 9) { if (n9 < 3) nine[n9++] = i; }
    }
    const float* x  = (const float*)d_in[ix];
    const float* W1 = (const float*)d_in[iW1];
    const float* b1 = (const float*)d_in[ib1];
    const float* W2 = (const float*)d_in[iW2];
    const float* b2 = (const float*)d_in[ib2];
    const float* W3 = (const float*)d_in[iW3];
    const float* b3 = (const float*)d_in[nine[0]];
    const float* st = (const float*)d_in[nine[1]];
    const float* et = (const float*)d_in[nine[2]];
    const float* tr = (const float*)d_in[itr];
    float* out = (float*)d_out;

    // Occupancy pad: 30KB unused dynamic smem -> static(47.8K)+dyn(30K)=77.8K
    // -> 2 blocks/SM (consumer SM hosts chain + only ONE MLP block).
    // Attribute call proven harmless in this harness (used in R1-R3 runs).
    int dyn = OCC_PAD;
    if (cudaFuncSetAttribute((const void*)fused_kernel,
            cudaFuncAttributeMaxDynamicSharedMemorySize, OCC_PAD) != cudaSuccess)
        dyn = 0;   // fallback: exactly the proven R15 configuration

    init_kernel<<<32, 256>>>();
    fused_kernel<<<64 + (B_ * T_) / TOK, 256, dyn>>>(x, W1, b1, W2, b2, W3, b3,
                                                     st, et, tr, out);
}